// round 5
// baseline (speedup 1.0000x reference)
#include <cuda_runtime.h>

namespace {

constexpr int KNN  = 32;   // K nearest neighbors
constexpr int IN2  = 64;   // 2K MLP input
constexpr int MID  = 32;   // hidden width of fc2
constexpr int QH   = 8;    // hidden units per thread (4 threads per element)

__device__ __forceinline__ float fast_tanh(float x) {
    float y;
    asm("tanh.approx.f32 %0, %1;" : "=f"(y) : "f"(x));
    return y;
}

// Flags for "first occurrence of a nonzero label" on rows k ≡ Q (mod 4).
// Compile-time Q keeps every inner loop bound constant -> fully unrolled,
// branch-free predicated ISETPs.
template <int Q>
__device__ __forceinline__ unsigned row_flags(const int* __restrict__ v) {
    unsigned f = 0u;
    #pragma unroll
    for (int m = 0; m < 8; m++) {
        constexpr int dummy = 0; (void)dummy;
        const int k = Q + 4 * m;
        bool dup = (v[k] == 0);
        #pragma unroll
        for (int j = 0; j < Q + 4 * m; j++) dup = dup || (v[j] == v[k]);
        if (!dup) f |= (1u << k);
    }
    return f;
}

__global__ __launch_bounds__(128) void meta_kernel(
    const int*   __restrict__ vals,
    const float* __restrict__ dist,
    const float* __restrict__ w1,   // [64,32]
    const float* __restrict__ b1,   // [32]
    const float* __restrict__ w2,   // [32,2]
    const float* __restrict__ b2,   // [2]
    const float* __restrict__ fw1,  // [2,4]
    const float* __restrict__ fb1,  // [4]
    const float* __restrict__ fw2,  // [4,1]
    const float* __restrict__ fb2,  // [1]
    float* __restrict__ out,        // [n,3]
    int n)
{
    __shared__ float s_w1[IN2 * MID];
    __shared__ float s_b1[MID];
    __shared__ float s_w2[MID * 2];

    {
        const int tid = threadIdx.x;
        for (int i = tid; i < IN2 * MID; i += blockDim.x) s_w1[i] = w1[i];
        if (tid < MID)     s_b1[tid] = b1[tid];
        if (tid < MID * 2) s_w2[tid] = w2[tid];
        __syncthreads();
    }

    const int gt      = blockIdx.x * blockDim.x + threadIdx.x;
    const int e       = gt >> 2;        // element index
    const int quarter = gt & 3;         // which 8 hidden units this thread owns
    if (e >= n) return;
    const int off = quarter * QH;

    // ---- init accumulators with bias slice ----
    float h[QH];
    {
        float4 b0 = *reinterpret_cast<const float4*>(s_b1 + off);
        float4 b4 = *reinterpret_cast<const float4*>(s_b1 + off + 4);
        h[0] = b0.x; h[1] = b0.y; h[2] = b0.z; h[3] = b0.w;
        h[4] = b4.x; h[5] = b4.y; h[6] = b4.z; h[7] = b4.w;
    }

    // ---- phase A: distances -> FMA directly into h ----
    {
        const float4* dp = reinterpret_cast<const float4*>(dist + (size_t)e * KNN);
        #pragma unroll
        for (int c = 0; c < KNN / 4; c++) {
            float4 d4 = dp[c];
            float xs[4] = {d4.x, d4.y, d4.z, d4.w};
            #pragma unroll
            for (int r = 0; r < 4; r++) {
                const float xi = xs[r];
                const float* wr = s_w1 + (c * 4 + r) * MID + off;
                float4 wa = *reinterpret_cast<const float4*>(wr);
                float4 wb = *reinterpret_cast<const float4*>(wr + 4);
                h[0] = fmaf(xi, wa.x, h[0]);
                h[1] = fmaf(xi, wa.y, h[1]);
                h[2] = fmaf(xi, wa.z, h[2]);
                h[3] = fmaf(xi, wa.w, h[3]);
                h[4] = fmaf(xi, wb.x, h[4]);
                h[5] = fmaf(xi, wb.y, h[5]);
                h[6] = fmaf(xi, wb.z, h[6]);
                h[7] = fmaf(xi, wb.w, h[7]);
            }
        }
    }

    // ---- phase B: cooperative label counting across the quad ----
    {
        int v[KNN];
        const int4* vp = reinterpret_cast<const int4*>(vals + (size_t)e * KNN);
        #pragma unroll
        for (int c = 0; c < KNN / 4; c++) {
            int4 t = vp[c];
            v[4*c+0] = t.x; v[4*c+1] = t.y; v[4*c+2] = t.z; v[4*c+3] = t.w;
        }

        unsigned flags;
        switch (quarter) {
            case 0:  flags = row_flags<0>(v); break;
            case 1:  flags = row_flags<1>(v); break;
            case 2:  flags = row_flags<2>(v); break;
            default: flags = row_flags<3>(v); break;
        }
        flags |= __shfl_xor_sync(0xffffffffu, flags, 1);
        flags |= __shfl_xor_sync(0xffffffffu, flags, 2);

        // counts: cnt_k = popc(bits 0..k of flags); FMA into h
        #pragma unroll
        for (int k = 0; k < KNN; k++) {
            const float cf = (float)__popc(flags << (31 - k));
            const float* wr = s_w1 + (KNN + k) * MID + off;
            float4 wa = *reinterpret_cast<const float4*>(wr);
            float4 wb = *reinterpret_cast<const float4*>(wr + 4);
            h[0] = fmaf(cf, wa.x, h[0]);
            h[1] = fmaf(cf, wa.y, h[1]);
            h[2] = fmaf(cf, wa.z, h[2]);
            h[3] = fmaf(cf, wa.w, h[3]);
            h[4] = fmaf(cf, wb.x, h[4]);
            h[5] = fmaf(cf, wb.y, h[5]);
            h[6] = fmaf(cf, wb.z, h[6]);
            h[7] = fmaf(cf, wb.w, h[7]);
        }
    }

    // ---- fc2 layer 2: partial sums over this thread's 8 hidden units ----
    float p0 = 0.f, p1 = 0.f;
    #pragma unroll
    for (int j = 0; j < QH; j++) {
        const float t = fast_tanh(h[j]);
        p0 = fmaf(t, s_w2[2 * (off + j) + 0], p0);
        p1 = fmaf(t, s_w2[2 * (off + j) + 1], p1);
    }
    p0 += __shfl_xor_sync(0xffffffffu, p0, 1);
    p1 += __shfl_xor_sync(0xffffffffu, p1, 1);
    p0 += __shfl_xor_sync(0xffffffffu, p0, 2);
    p1 += __shfl_xor_sync(0xffffffffu, p1, 2);

    // ---- fc1 + store (lane 0 of the quad only) ----
    if (quarter == 0) {
        const float o0 = p0 + b2[0];
        const float o1 = p1 + b2[1];
        float o2 = fb2[0];
        #pragma unroll
        for (int m = 0; m < 4; m++) {
            const float t = fast_tanh(fb1[m] + fmaf(o0, fw1[m], o1 * fw1[4 + m]));
            o2 = fmaf(t, fw2[m], o2);
        }
        out[3*e+0] = o0;
        out[3*e+1] = o1;
        out[3*e+2] = o2;
    }
}

} // anonymous namespace

extern "C" void kernel_launch(void* const* d_in, const int* in_sizes, int n_in,
                              void* d_out, int out_size) {
    const int*   vals = (const int*)  d_in[0];
    const float* dist = (const float*)d_in[1];
    const float* w1   = (const float*)d_in[2];
    const float* b1   = (const float*)d_in[3];
    const float* w2   = (const float*)d_in[4];
    const float* b2   = (const float*)d_in[5];
    const float* fw1  = (const float*)d_in[6];
    const float* fb1  = (const float*)d_in[7];
    const float* fw2  = (const float*)d_in[8];
    const float* fb2  = (const float*)d_in[9];
    float* out = (float*)d_out;

    const int n = in_sizes[0] / KNN;        // B*S elements
    const int total = 4 * n;                // 4 threads per element
    const int threads = 128;
    const int blocks = (total + threads - 1) / threads;
    meta_kernel<<<blocks, threads>>>(vals, dist, w1, b1, w2, b2,
                                     fw1, fb1, fw2, fb2, out, n);
}